// round 14
// baseline (speedup 1.0000x reference)
#include <cuda_runtime.h>

// MVGeometricProduct — fine-grained pipeline round (3rd submit; two prior runs infra-failed).
// R11 (14.4us): register double-buffer hid DRAM latency but 2-block cap left only
// 16 warps/SM; 46% stall fraction remains (normalize dep chains).
// Now: pipeline granule = ONE site (prefetch buffer 4 float4 = 16 regs), so base+buffer
// ~80 regs fits __launch_bounds__(256,3): 24 warps/SM AND pipelining.
// Grid = (3, 148) = 444 blocks ≈ one wave at 3 blocks/SM; ~7 sites/thread.

#define NR 256
#define PADW 21

__device__ __forceinline__ void normalize8(const float* ww,
                                           float s0, float s1, float s2, float s3,
                                           float* wn) {
    float nrm0 = fabsf(ww[0]);
    float nrm1 = __fsqrt_rn(ww[1]*ww[1] + ww[2]*ww[2] + ww[3]*ww[3]);
    float nrm2 = __fsqrt_rn(ww[4]*ww[4] + ww[5]*ww[5] + ww[6]*ww[6]);
    float nrm3 = fabsf(ww[7]);
    float r0 = __fdividef(1.0f, fmaf(s0, nrm0 - 1.0f, 1.0f));
    float r1 = __fdividef(1.0f, fmaf(s1, nrm1 - 1.0f, 1.0f));
    float r2 = __fdividef(1.0f, fmaf(s2, nrm2 - 1.0f, 1.0f));
    float r3 = __fdividef(1.0f, fmaf(s3, nrm3 - 1.0f, 1.0f));
    wn[0] = ww[0] * r0;
    wn[1] = ww[1] * r1;  wn[2] = ww[2] * r1;  wn[3] = ww[3] * r1;
    wn[4] = ww[4] * r2;  wn[5] = ww[5] * r2;  wn[6] = ww[6] * r2;
    wn[7] = ww[7] * r3;
}

__device__ __forceinline__ void site_compute(const float* vi, const float* wn,
                                             const float* wt, float* o) {
#pragma unroll
    for (int t = 0; t < 8; ++t) o[t] = 0.0f;
#define T(I, K, J, S, P) o[J] = fmaf((S) * wt[P] * vi[I], wn[K], o[J]);
    // i = 0 (scalar)
    T(0,0,0, 1.f, 0)  T(0,1,1, 1.f, 1)  T(0,2,2, 1.f, 1)  T(0,3,3, 1.f, 1)
    T(0,4,4, 1.f, 2)  T(0,5,5, 1.f, 2)  T(0,6,6, 1.f, 2)  T(0,7,7, 1.f, 3)
    // i = 1 (e1)
    T(1,0,1, 1.f, 5)  T(1,1,0, 1.f, 4)  T(1,2,4, 1.f, 7)  T(1,3,5, 1.f, 7)
    T(1,4,2, 1.f, 6)  T(1,5,3, 1.f, 6)  T(1,6,7, 1.f, 9)  T(1,7,6, 1.f, 8)
    // i = 2 (e2)
    T(2,0,2, 1.f, 5)  T(2,1,4,-1.f, 7)  T(2,2,0, 1.f, 4)  T(2,3,6, 1.f, 7)
    T(2,4,1,-1.f, 6)  T(2,5,7,-1.f, 9)  T(2,6,3, 1.f, 6)  T(2,7,5,-1.f, 8)
    // i = 3 (e3)
    T(3,0,3, 1.f, 5)  T(3,1,5,-1.f, 7)  T(3,2,6,-1.f, 7)  T(3,3,0, 1.f, 4)
    T(3,4,7, 1.f, 9)  T(3,5,1,-1.f, 6)  T(3,6,2,-1.f, 6)  T(3,7,4, 1.f, 8)
    // i = 4 (e12)
    T(4,0,4,-1.f,13)  T(4,1,2, 1.f,11)  T(4,2,1,-1.f,11)  T(4,3,7,-1.f,15)
    T(4,4,0, 1.f,10)  T(4,5,6, 1.f,14)  T(4,6,5,-1.f,14)  T(4,7,3, 1.f,12)
    // i = 5 (e13)
    T(5,0,5,-1.f,13)  T(5,1,3, 1.f,11)  T(5,2,7, 1.f,15)  T(5,3,1,-1.f,11)
    T(5,4,6,-1.f,14)  T(5,5,0, 1.f,10)  T(5,6,4, 1.f,14)  T(5,7,2,-1.f,12)
    // i = 6 (e23)
    T(6,0,6,-1.f,13)  T(6,1,7,-1.f,15)  T(6,2,3, 1.f,11)  T(6,3,2,-1.f,11)
    T(6,4,5, 1.f,14)  T(6,5,4,-1.f,14)  T(6,6,0, 1.f,10)  T(6,7,1, 1.f,12)
    // i = 7 (e123)
    T(7,0,7,-1.f,19)  T(7,1,6,-1.f,18)  T(7,2,5, 1.f,18)  T(7,3,4,-1.f,18)
    T(7,4,3, 1.f,17)  T(7,5,2,-1.f,17)  T(7,6,1, 1.f,17)  T(7,7,0, 1.f,16)
#undef T
}

__global__ __launch_bounds__(NR, 3) void mv_gp_kernel(
    const float* __restrict__ v,
    const float* __restrict__ w,
    const float* __restrict__ weight,
    const float* __restrict__ a,
    float* __restrict__ out,
    int B, int F, int GY)
{
    __shared__ float wt_s[NR * PADW];   // row-major, padded (gcd(21,32)=1)

    const int tid = threadIdx.x;
    const int n0  = blockIdx.x * NR;

    // ---- stage weight rows: coalesced float4 reads, scalar padded writes ----
    {
        const float4* wsrc = (const float4*)(weight + (size_t)n0 * 20);
#pragma unroll
        for (int it = 0; it < 5; ++it) {
            int i = tid + it * NR;          // 1280 float4 total
            float4 x = wsrc[i];
            int e = i * 4;
            int base = (e / 20) * PADW + (e % 20);
            wt_s[base + 0] = x.x;
            wt_s[base + 1] = x.y;
            wt_s[base + 2] = x.z;
            wt_s[base + 3] = x.w;
        }
    }

    const int n = n0 + tid;

    // sigmoid(a[n]) — once per thread
    const float4 a4 = *(const float4*)(a + (size_t)n * 4);
    const float s0 = __fdividef(1.0f, 1.0f + __expf(-a4.x));
    const float s1 = __fdividef(1.0f, 1.0f + __expf(-a4.y));
    const float s2 = __fdividef(1.0f, 1.0f + __expf(-a4.z));
    const float s3 = __fdividef(1.0f, 1.0f + __expf(-a4.w));

    __syncthreads();

    // per-thread weight row (conflict-free: stride 21) — once per thread
    float wt[20];
    const float* wrow = &wt_s[tid * PADW];
#pragma unroll
    for (int p = 0; p < 20; ++p) wt[p] = wrow[p];

    int b = blockIdx.y;
    if (b >= B) return;

    const size_t stride = (size_t)GY * F;   // site stride per loop step
    size_t site = (size_t)b * F + n;

    // ---- prologue: load first site ----
    const float4* pv = (const float4*)(v + site * 8);
    const float4* pw = (const float4*)(w + site * 8);
    float4 cv0 = pv[0], cv1 = pv[1];
    float4 cw0 = pw[0], cw1 = pw[1];

    // ---- pipelined loop: one site per iteration ----
    for (;;) {
        const int nb = b + GY;
        const bool more = (nb < B);

        float4 nv0, nv1, nw0, nw1;
        const size_t nsite = site + stride;
        if (more) {
            const float4* qv = (const float4*)(v + nsite * 8);
            const float4* qw = (const float4*)(w + nsite * 8);
            nv0 = qv[0]; nv1 = qv[1];
            nw0 = qw[0]; nw1 = qw[1];
        }

        // compute + store current site
        {
            float vi[8] = {cv0.x, cv0.y, cv0.z, cv0.w, cv1.x, cv1.y, cv1.z, cv1.w};
            float ww[8] = {cw0.x, cw0.y, cw0.z, cw0.w, cw1.x, cw1.y, cw1.z, cw1.w};
            float wn[8], o[8];
            normalize8(ww, s0, s1, s2, s3, wn);
            site_compute(vi, wn, wt, o);
            float4* o4 = (float4*)(out + site * 8);
            o4[0] = make_float4(o[0], o[1], o[2], o[3]);
            o4[1] = make_float4(o[4], o[5], o[6], o[7]);
        }

        if (!more) break;

        b = nb; site = nsite;
        cv0 = nv0; cv1 = nv1; cw0 = nw0; cw1 = nw1;
    }
}

extern "C" void kernel_launch(void* const* d_in, const int* in_sizes, int n_in,
                              void* d_out, int out_size) {
    const float* v      = (const float*)d_in[0];
    const float* w      = (const float*)d_in[1];
    const float* weight = (const float*)d_in[2];
    const float* a      = (const float*)d_in[3];
    float* out = (float*)d_out;

    int F     = in_sizes[3] / 4;        // a is [F, 4]
    int total = in_sizes[0] / 8;        // B * F
    int B     = total / F;

    int gx = F / NR;                    // 3
    // one wave at 3 blocks/SM: 148*3 / gx
    int gy = (148 * 3) / (gx > 0 ? gx : 1);
    if (gy > B) gy = B;
    if (gy < 1) gy = 1;

    dim3 grid(gx, gy);
    mv_gp_kernel<<<grid, NR>>>(v, w, weight, a, out, B, F, gy);
}